// round 1
// baseline (speedup 1.0000x reference)
#include <cuda_runtime.h>
#include <cstdint>

#define NP 100000
#define NA 50000
#define DD 128
#define EE 500000

// ---------------- device scratch (no cudaMalloc allowed) ----------------
__device__ float g_agg1[(size_t)NP * DD];   // cites mean accumulator (papers)
__device__ float g_agg2[(size_t)NP * DD];   // writes mean accumulator (papers)
__device__ float g_agga[(size_t)NA * DD];   // rev mean accumulator (authors)
__device__ float g_cnt1[NP];
__device__ float g_cnt2[NP];
__device__ float g_cnta[NA];
__device__ float g_pnew[(size_t)NP * DD];
__device__ float g_anew[(size_t)NA * DD];
__device__ float g_xp[(size_t)NP * DD];
__device__ float g_xa[(size_t)NA * DD];
__device__ float g_wp_raw[384 * 128];
__device__ float g_wp_eff[384 * 128];
__device__ float g_wa_raw[256 * 128];
__device__ float g_wa_eff[256 * 128];
__device__ float g_bp_raw[128];
__device__ float g_bp_eff[128];
__device__ float g_ba_raw[128];
__device__ float g_ba_eff[128];

// ---------------- counts ----------------
__global__ void count_kernel(const int* __restrict__ dst, float* __restrict__ cnt, int E) {
    int e = blockIdx.x * blockDim.x + threadIdx.x;
    if (e < E) atomicAdd(cnt + dst[e], 1.0f);
}

__global__ void inv_kernel(float* __restrict__ cnt, int n) {
    int i = blockIdx.x * blockDim.x + threadIdx.x;
    if (i < n) cnt[i] = 1.0f / fmaxf(cnt[i], 1.0f);
}

// ---------------- edge scatter: warp per edge ----------------
__global__ __launch_bounds__(256) void scatter_kernel(
    const float* __restrict__ x, const int* __restrict__ src,
    const int* __restrict__ dst, float* __restrict__ agg, int E)
{
    int warp = (blockIdx.x * blockDim.x + threadIdx.x) >> 5;
    int lane = threadIdx.x & 31;
    if (warp >= E) return;
    int s = __ldg(src + warp);
    int d = __ldg(dst + warp);
    float4 v = __ldg((const float4*)(x + (size_t)s * DD) + lane);
    float* p = agg + (size_t)d * DD + lane * 4;
    asm volatile("red.global.add.v4.f32 [%0], {%1,%2,%3,%4};"
                 :: "l"(p), "f"(v.x), "f"(v.y), "f"(v.z), "f"(v.w) : "memory");
}

// ---------------- weight prep ----------------
// Wcat_p[k][j] (k in [0,384)): seg0 = Wl[l,0]^T, seg1 = Wl[l,1]^T, seg2 = (Wr[l,0]+Wr[l,1])^T
__global__ void prep_w_p(const float* __restrict__ Wl, const float* __restrict__ Wr,
                         float* __restrict__ wout, int l)
{
    int idx = blockIdx.x * blockDim.x + threadIdx.x;
    if (idx >= 384 * 128) return;
    int k = idx >> 7, j = idx & 127;
    int seg = k >> 7, kk = k & 127;
    float v;
    if (seg == 0)      v = Wl[(size_t)((l * 3 + 0) * 128 + j) * 128 + kk];
    else if (seg == 1) v = Wl[(size_t)((l * 3 + 1) * 128 + j) * 128 + kk];
    else               v = Wr[(size_t)((l * 3 + 0) * 128 + j) * 128 + kk]
                         + Wr[(size_t)((l * 3 + 1) * 128 + j) * 128 + kk];
    wout[idx] = v;
}

// Wcat_a[k][j] (k in [0,256)): seg0 = Wl[l,2]^T, seg1 = Wr[l,2]^T
__global__ void prep_w_a(const float* __restrict__ Wl, const float* __restrict__ Wr,
                         float* __restrict__ wout, int l)
{
    int idx = blockIdx.x * blockDim.x + threadIdx.x;
    if (idx >= 256 * 128) return;
    int k = idx >> 7, j = idx & 127;
    int seg = k >> 7, kk = k & 127;
    float v;
    if (seg == 0) v = Wl[(size_t)((l * 3 + 2) * 128 + j) * 128 + kk];
    else          v = Wr[(size_t)((l * 3 + 2) * 128 + j) * 128 + kk];
    wout[idx] = v;
}

__global__ void prep_bias(const float* __restrict__ bl, float* __restrict__ bp,
                          float* __restrict__ ba, int l)
{
    int j = threadIdx.x;
    if (j < 128) {
        bp[j] = bl[(l * 3 + 0) * 128 + j] + bl[(l * 3 + 1) * 128 + j];
        ba[j] = bl[(l * 3 + 2) * 128 + j];
    }
}

// Fold residual: wout[k][j] = win[k][j] + sum_m win[k][m] * lin[j][m]   (z + z@lin^T)
__global__ void fold_w(const float* __restrict__ win, const float* __restrict__ lin,
                       float* __restrict__ wout, int K)
{
    int idx = blockIdx.x * blockDim.x + threadIdx.x;
    if (idx >= K * 128) return;
    int k = idx >> 7, j = idx & 127;
    const float* wr = win + (size_t)k * 128;
    const float* lr = lin + (size_t)j * 128;
    float s = wr[j];
    #pragma unroll 4
    for (int m = 0; m < 128; m++) s += __ldg(wr + m) * __ldg(lr + m);
    wout[idx] = s;
}

__global__ void fold_b(const float* __restrict__ bin, const float* __restrict__ lin,
                       float* __restrict__ bout)
{
    int j = threadIdx.x;
    if (j >= 128) return;
    const float* lr = lin + (size_t)j * 128;
    float s = bin[j];
    for (int m = 0; m < 128; m++) s += bin[m] * lr[m];
    bout[j] = s;
}

// ---------------- segmented SGEMM: C[M,128] = [A0*s0 | A1*s1 | A2] @ W + bias ----------------
// W is [nseg*128, 128] row-major. A tiles are 128-col row-major. s* = per-row scale (null -> 1).
#define BM 128
#define BK 16
__global__ __launch_bounds__(256) void gemm_sage(
    const float* __restrict__ A0, const float* __restrict__ A1, const float* __restrict__ A2,
    const float* __restrict__ s0, const float* __restrict__ s1,
    const float* __restrict__ W, const float* __restrict__ bias,
    float* __restrict__ C, int M, int nseg)
{
    __shared__ float As[BK][132];
    __shared__ float Bs[BK][128];
    int tid = threadIdx.x;
    int tx = tid & 15;       // n dim (8 cols each)
    int ty = tid >> 4;       // m dim (8 rows each)
    int rowBase = blockIdx.x * BM;

    const float* Aseg[3] = {A0, A1, A2};
    const float* Sseg[3] = {s0, s1, nullptr};

    float acc[8][8];
    #pragma unroll
    for (int i = 0; i < 8; i++)
        #pragma unroll
        for (int j = 0; j < 8; j++) acc[i][j] = 0.0f;

    int K = nseg * 128;
    for (int k0 = 0; k0 < K; k0 += BK) {
        int seg = k0 >> 7;
        int kloc = k0 & 127;
        const float* A = Aseg[seg];
        const float* S = Sseg[seg];
        // A tile: 128 rows x 16 k, each thread 2 float4
        #pragma unroll
        for (int i = 0; i < 2; i++) {
            int idx = tid + i * 256;
            int r = idx >> 2;
            int c4 = idx & 3;
            int grow = rowBase + r;
            float4 v = make_float4(0.f, 0.f, 0.f, 0.f);
            float sc = 1.0f;
            if (grow < M) {
                v = __ldg((const float4*)(A + (size_t)grow * DD + kloc) + c4);
                if (S) sc = __ldg(S + grow);
            }
            As[c4 * 4 + 0][r] = v.x * sc;
            As[c4 * 4 + 1][r] = v.y * sc;
            As[c4 * 4 + 2][r] = v.z * sc;
            As[c4 * 4 + 3][r] = v.w * sc;
        }
        // B tile: 16 k x 128 n
        #pragma unroll
        for (int i = 0; i < 2; i++) {
            int idx = tid + i * 256;
            int kk = idx >> 5;
            int n4 = idx & 31;
            float4 v = __ldg((const float4*)(W + (size_t)(k0 + kk) * 128) + n4);
            *((float4*)&Bs[kk][n4 * 4]) = v;
        }
        __syncthreads();
        #pragma unroll
        for (int kk = 0; kk < BK; kk++) {
            float a[8], b[8];
            *(float4*)&a[0] = *(const float4*)&As[kk][ty * 8];
            *(float4*)&a[4] = *(const float4*)&As[kk][ty * 8 + 4];
            *(float4*)&b[0] = *(const float4*)&Bs[kk][tx * 8];
            *(float4*)&b[4] = *(const float4*)&Bs[kk][tx * 8 + 4];
            #pragma unroll
            for (int i = 0; i < 8; i++)
                #pragma unroll
                for (int j = 0; j < 8; j++)
                    acc[i][j] += a[i] * b[j];
        }
        __syncthreads();
    }

    float bf[8];
    *(float4*)&bf[0] = __ldg((const float4*)(bias + tx * 8));
    *(float4*)&bf[4] = __ldg((const float4*)(bias + tx * 8 + 4));
    #pragma unroll
    for (int i = 0; i < 8; i++) {
        int grow = rowBase + ty * 8 + i;
        if (grow < M) {
            float4 v0, v1;
            v0.x = acc[i][0] + bf[0]; v0.y = acc[i][1] + bf[1];
            v0.z = acc[i][2] + bf[2]; v0.w = acc[i][3] + bf[3];
            v1.x = acc[i][4] + bf[4]; v1.y = acc[i][5] + bf[5];
            v1.z = acc[i][6] + bf[6]; v1.w = acc[i][7] + bf[7];
            *((float4*)(C + (size_t)grow * DD + tx * 8))     = v0;
            *((float4*)(C + (size_t)grow * DD + tx * 8 + 4)) = v1;
        }
    }
}

// ---------------- LayerNorm + ReLU (warp per row) ----------------
__global__ __launch_bounds__(256) void ln_relu_kernel(
    const float* __restrict__ in, const float* __restrict__ g,
    const float* __restrict__ b, float* __restrict__ out, int M)
{
    int gtid = blockIdx.x * blockDim.x + threadIdx.x;
    int row = gtid >> 5, lane = gtid & 31;
    if (row >= M) return;
    float4 v = __ldg((const float4*)(in + (size_t)row * DD) + lane);
    float s  = v.x + v.y + v.z + v.w;
    float sq = v.x * v.x + v.y * v.y + v.z * v.z + v.w * v.w;
    #pragma unroll
    for (int o = 16; o > 0; o >>= 1) {
        s  += __shfl_xor_sync(0xFFFFFFFFu, s, o);
        sq += __shfl_xor_sync(0xFFFFFFFFu, sq, o);
    }
    float m = s * (1.0f / 128.0f);
    float var = sq * (1.0f / 128.0f) - m * m;
    float r = rsqrtf(var + 1e-5f);
    float4 gg = __ldg((const float4*)g + lane);
    float4 bb = __ldg((const float4*)b + lane);
    float4 o4;
    o4.x = fmaxf((v.x - m) * r * gg.x + bb.x, 0.0f);
    o4.y = fmaxf((v.y - m) * r * gg.y + bb.y, 0.0f);
    o4.z = fmaxf((v.z - m) * r * gg.z + bb.z, 0.0f);
    o4.w = fmaxf((v.w - m) * r * gg.w + bb.w, 0.0f);
    ((float4*)(out + (size_t)row * DD))[lane] = o4;
}

// ---------------- head: out[M,16] = x[M,128] @ Wh[128,16] + bh ----------------
__global__ __launch_bounds__(256) void head_kernel(
    const float* __restrict__ x, const float* __restrict__ Wh,
    const float* __restrict__ bh, float* __restrict__ out, int M)
{
    __shared__ float WsT[16 * 128];   // [c][k]
    __shared__ float bs[16];
    for (int i = threadIdx.x; i < 2048; i += 256) {
        int c = i >> 7, k = i & 127;
        WsT[i] = Wh[k * 16 + c];
    }
    if (threadIdx.x < 16) bs[threadIdx.x] = bh[threadIdx.x];
    __syncthreads();
    int warp = threadIdx.x >> 5, lane = threadIdx.x & 31;
    int row = blockIdx.x * 8 + warp;
    if (row >= M) return;
    float4 v = __ldg((const float4*)(x + (size_t)row * DD) + lane);
    float acc[16];
    #pragma unroll
    for (int c = 0; c < 16; c++) {
        float4 w = ((const float4*)(WsT + c * 128))[lane];
        acc[c] = v.x * w.x + v.y * w.y + v.z * w.z + v.w * w.w;
    }
    #pragma unroll
    for (int c = 0; c < 16; c++)
        #pragma unroll
        for (int o = 16; o > 0; o >>= 1)
            acc[c] += __shfl_xor_sync(0xFFFFFFFFu, acc[c], o);
    if (lane == 0) {
        #pragma unroll
        for (int c = 0; c < 16; c++)
            out[(size_t)row * 16 + c] = acc[c] + bs[c];
    }
}

// ---------------- launch ----------------
extern "C" void kernel_launch(void* const* d_in, const int* in_sizes, int n_in,
                              void* d_out, int out_size)
{
    const float* x_paper  = (const float*)d_in[0];
    const float* x_author = (const float*)d_in[1];
    const int*   ei_c     = (const int*)d_in[2];
    const int*   ei_w     = (const int*)d_in[3];
    const int*   ei_r     = (const int*)d_in[4];
    const float* Wl       = (const float*)d_in[5];
    const float* Wr       = (const float*)d_in[6];
    const float* bl       = (const float*)d_in[7];
    const float* lin_p    = (const float*)d_in[8];
    const float* lin_a    = (const float*)d_in[9];
    const float* ln_s     = (const float*)d_in[10];
    const float* ln_b     = (const float*)d_in[11];
    const float* Wh       = (const float*)d_in[12];
    const float* bh       = (const float*)d_in[13];
    float* out = (float*)d_out;

    float *agg1, *agg2, *agga, *cnt1, *cnt2, *cnta, *pnew, *anew, *xp, *xa;
    float *wp_raw, *wp_eff, *wa_raw, *wa_eff, *bp_raw, *bp_eff, *ba_raw, *ba_eff;
    cudaGetSymbolAddress((void**)&agg1, g_agg1);
    cudaGetSymbolAddress((void**)&agg2, g_agg2);
    cudaGetSymbolAddress((void**)&agga, g_agga);
    cudaGetSymbolAddress((void**)&cnt1, g_cnt1);
    cudaGetSymbolAddress((void**)&cnt2, g_cnt2);
    cudaGetSymbolAddress((void**)&cnta, g_cnta);
    cudaGetSymbolAddress((void**)&pnew, g_pnew);
    cudaGetSymbolAddress((void**)&anew, g_anew);
    cudaGetSymbolAddress((void**)&xp, g_xp);
    cudaGetSymbolAddress((void**)&xa, g_xa);
    cudaGetSymbolAddress((void**)&wp_raw, g_wp_raw);
    cudaGetSymbolAddress((void**)&wp_eff, g_wp_eff);
    cudaGetSymbolAddress((void**)&wa_raw, g_wa_raw);
    cudaGetSymbolAddress((void**)&wa_eff, g_wa_eff);
    cudaGetSymbolAddress((void**)&bp_raw, g_bp_raw);
    cudaGetSymbolAddress((void**)&bp_eff, g_bp_eff);
    cudaGetSymbolAddress((void**)&ba_raw, g_ba_raw);
    cudaGetSymbolAddress((void**)&ba_eff, g_ba_eff);

    const int E = EE;
    // ---- counts (fixed across layers) ----
    cudaMemsetAsync(cnt1, 0, NP * sizeof(float), 0);
    cudaMemsetAsync(cnt2, 0, NP * sizeof(float), 0);
    cudaMemsetAsync(cnta, 0, NA * sizeof(float), 0);
    count_kernel<<<(E + 255) / 256, 256>>>(ei_c + E, cnt1, E);
    count_kernel<<<(E + 255) / 256, 256>>>(ei_w + E, cnt2, E);
    count_kernel<<<(E + 255) / 256, 256>>>(ei_r + E, cnta, E);
    inv_kernel<<<(NP + 255) / 256, 256>>>(cnt1, NP);
    inv_kernel<<<(NP + 255) / 256, 256>>>(cnt2, NP);
    inv_kernel<<<(NA + 255) / 256, 256>>>(cnta, NA);

    int gridP = (NP + BM - 1) / BM;   // 782
    int gridA = (NA + BM - 1) / BM;   // 391
    int gridScat = (E + 7) / 8;

    // ================= LAYER 0 =================
    prep_w_p<<<(384 * 128) / 256, 256>>>(Wl, Wr, wp_raw, 0);
    prep_w_a<<<(256 * 128) / 256, 256>>>(Wl, Wr, wa_raw, 0);
    prep_bias<<<1, 128>>>(bl, bp_raw, ba_raw, 0);
    // fold layer-0 residual (z + z@lin^T) into weights/bias
    fold_w<<<(384 * 128) / 256, 256>>>(wp_raw, lin_p, wp_eff, 384);
    fold_w<<<(256 * 128) / 256, 256>>>(wa_raw, lin_a, wa_eff, 256);
    fold_b<<<1, 128>>>(bp_raw, lin_p, bp_eff);
    fold_b<<<1, 128>>>(ba_raw, lin_a, ba_eff);

    cudaMemsetAsync(agg1, 0, (size_t)NP * DD * sizeof(float), 0);
    cudaMemsetAsync(agg2, 0, (size_t)NP * DD * sizeof(float), 0);
    cudaMemsetAsync(agga, 0, (size_t)NA * DD * sizeof(float), 0);
    scatter_kernel<<<gridScat, 256>>>(x_paper,  ei_c, ei_c + E, agg1, E);
    scatter_kernel<<<gridScat, 256>>>(x_author, ei_w, ei_w + E, agg2, E);
    scatter_kernel<<<gridScat, 256>>>(x_paper,  ei_r, ei_r + E, agga, E);

    gemm_sage<<<gridP, 256>>>(agg1, agg2, x_paper, cnt1, cnt2, wp_eff, bp_eff, pnew, NP, 3);
    gemm_sage<<<gridA, 256>>>(agga, x_author, nullptr, cnta, nullptr, wa_eff, ba_eff, anew, NA, 2);

    ln_relu_kernel<<<((size_t)NP * 32 + 255) / 256, 256>>>(pnew, ln_s + 0,   ln_b + 0,   xp, NP);
    ln_relu_kernel<<<((size_t)NA * 32 + 255) / 256, 256>>>(anew, ln_s + 128, ln_b + 128, xa, NA);

    // ================= LAYER 1 (author path dead -> skipped) =================
    prep_w_p<<<(384 * 128) / 256, 256>>>(Wl, Wr, wp_raw, 1);
    prep_bias<<<1, 128>>>(bl, bp_raw, ba_raw, 1);

    cudaMemsetAsync(agg1, 0, (size_t)NP * DD * sizeof(float), 0);
    cudaMemsetAsync(agg2, 0, (size_t)NP * DD * sizeof(float), 0);
    scatter_kernel<<<gridScat, 256>>>(xp, ei_c, ei_c + E, agg1, E);
    scatter_kernel<<<gridScat, 256>>>(xa, ei_w, ei_w + E, agg2, E);

    gemm_sage<<<gridP, 256>>>(agg1, agg2, xp, cnt1, cnt2, wp_raw, bp_raw, pnew, NP, 3);
    ln_relu_kernel<<<((size_t)NP * 32 + 255) / 256, 256>>>(pnew, ln_s + 256, ln_b + 256, xp, NP);

    // ================= head =================
    head_kernel<<<(NP + 7) / 8, 256>>>(xp, Wh, bh, out, NP);

    (void)in_sizes; (void)n_in; (void)out_size;
}

// round 2
// speedup vs baseline: 1.4645x; 1.4645x over previous
#include <cuda_runtime.h>
#include <cstdint>

#define NP 100000
#define NA 50000
#define DD 128
#define EE 500000

// ---------------- device scratch (no cudaMalloc allowed) ----------------
__device__ float g_agg1[(size_t)NP * DD];
__device__ float g_agg2[(size_t)NP * DD];
__device__ float g_agga[(size_t)NA * DD];
__device__ float g_cnt1[NP];
__device__ float g_cnt2[NP];
__device__ float g_cnta[NA];
__device__ float g_xp[(size_t)NP * DD];
__device__ float g_xa[(size_t)NA * DD];
__device__ float g_wp_raw[384 * 128];
__device__ float g_wp_eff[384 * 128];
__device__ float g_wa_raw[256 * 128];
__device__ float g_wa_eff[256 * 128];
__device__ float g_bp_raw[128];
__device__ float g_bp_eff[128];
__device__ float g_ba_raw[128];
__device__ float g_ba_eff[128];

// ---------------- helpers ----------------
__device__ __forceinline__ float tf32r(float x) {
    uint32_t u;
    asm("cvt.rna.tf32.f32 %0, %1;" : "=r"(u) : "f"(x));
    return __uint_as_float(u);
}
__device__ __forceinline__ uint32_t fu(float x) { return __float_as_uint(x); }

#define MMA_TF32(c, a, b) \
    asm volatile("mma.sync.aligned.m16n8k8.row.col.f32.tf32.tf32.f32 " \
                 "{%0,%1,%2,%3},{%4,%5,%6,%7},{%8,%9},{%0,%1,%2,%3};" \
                 : "+f"((c)[0]), "+f"((c)[1]), "+f"((c)[2]), "+f"((c)[3]) \
                 : "r"((a)[0]), "r"((a)[1]), "r"((a)[2]), "r"((a)[3]), \
                   "r"((b)[0]), "r"((b)[1]))

// ---------------- counts ----------------
__global__ void count_kernel(const int* __restrict__ dst, float* __restrict__ cnt, int E) {
    int e = blockIdx.x * blockDim.x + threadIdx.x;
    if (e < E) atomicAdd(cnt + dst[e], 1.0f);
}

__global__ void inv_kernel(float* __restrict__ cnt, int n) {
    int i = blockIdx.x * blockDim.x + threadIdx.x;
    if (i < n) cnt[i] = 1.0f / fmaxf(cnt[i], 1.0f);
}

// ---------------- edge scatter: warp per edge ----------------
__global__ __launch_bounds__(256) void scatter_kernel(
    const float* __restrict__ x, const int* __restrict__ src,
    const int* __restrict__ dst, float* __restrict__ agg, int E)
{
    int warp = (blockIdx.x * blockDim.x + threadIdx.x) >> 5;
    int lane = threadIdx.x & 31;
    if (warp >= E) return;
    int s = __ldg(src + warp);
    int d = __ldg(dst + warp);
    float4 v = __ldg((const float4*)(x + (size_t)s * DD) + lane);
    float* p = agg + (size_t)d * DD + lane * 4;
    asm volatile("red.global.add.v4.f32 [%0], {%1,%2,%3,%4};"
                 :: "l"(p), "f"(v.x), "f"(v.y), "f"(v.z), "f"(v.w) : "memory");
}

// ---------------- weight prep ----------------
__global__ void prep_w_p(const float* __restrict__ Wl, const float* __restrict__ Wr,
                         float* __restrict__ wout, int l)
{
    int idx = blockIdx.x * blockDim.x + threadIdx.x;
    if (idx >= 384 * 128) return;
    int k = idx >> 7, j = idx & 127;
    int seg = k >> 7, kk = k & 127;
    float v;
    if (seg == 0)      v = Wl[(size_t)((l * 3 + 0) * 128 + j) * 128 + kk];
    else if (seg == 1) v = Wl[(size_t)((l * 3 + 1) * 128 + j) * 128 + kk];
    else               v = Wr[(size_t)((l * 3 + 0) * 128 + j) * 128 + kk]
                         + Wr[(size_t)((l * 3 + 1) * 128 + j) * 128 + kk];
    wout[idx] = v;
}

__global__ void prep_w_a(const float* __restrict__ Wl, const float* __restrict__ Wr,
                         float* __restrict__ wout, int l)
{
    int idx = blockIdx.x * blockDim.x + threadIdx.x;
    if (idx >= 256 * 128) return;
    int k = idx >> 7, j = idx & 127;
    int seg = k >> 7, kk = k & 127;
    float v;
    if (seg == 0) v = Wl[(size_t)((l * 3 + 2) * 128 + j) * 128 + kk];
    else          v = Wr[(size_t)((l * 3 + 2) * 128 + j) * 128 + kk];
    wout[idx] = v;
}

__global__ void prep_bias(const float* __restrict__ bl, float* __restrict__ bp,
                          float* __restrict__ ba, int l)
{
    int j = threadIdx.x;
    if (j < 128) {
        bp[j] = bl[(l * 3 + 0) * 128 + j] + bl[(l * 3 + 1) * 128 + j];
        ba[j] = bl[(l * 3 + 2) * 128 + j];
    }
}

__global__ void fold_w(const float* __restrict__ win, const float* __restrict__ lin,
                       float* __restrict__ wout, int K)
{
    int idx = blockIdx.x * blockDim.x + threadIdx.x;
    if (idx >= K * 128) return;
    int k = idx >> 7, j = idx & 127;
    const float* wr = win + (size_t)k * 128;
    const float* lr = lin + (size_t)j * 128;
    float s = wr[j];
    #pragma unroll 4
    for (int m = 0; m < 128; m++) s += __ldg(wr + m) * __ldg(lr + m);
    wout[idx] = s;
}

__global__ void fold_b(const float* __restrict__ bin, const float* __restrict__ lin,
                       float* __restrict__ bout)
{
    int j = threadIdx.x;
    if (j >= 128) return;
    const float* lr = lin + (size_t)j * 128;
    float s = bin[j];
    for (int m = 0; m < 128; m++) s += bin[m] * lr[m];
    bout[j] = s;
}

// ---------------- tf32 tensor-core GEMM + fused bias + LayerNorm + ReLU ----------
// C[M,128] = LN_ReLU([A0*s0 | A1*s1 | A2] @ W + bias)
// W row-major [nseg*128, 128]. A tiles 128-col row-major. s* per-row scale.
#define BM 128
#define BKT 16
__global__ __launch_bounds__(256) void gemm_tf32_ln(
    const float* __restrict__ A0, const float* __restrict__ A1, const float* __restrict__ A2,
    const float* __restrict__ s0, const float* __restrict__ s1,
    const float* __restrict__ W, const float* __restrict__ bias,
    const float* __restrict__ lng, const float* __restrict__ lnb,
    float* __restrict__ Cout, int M, int nseg)
{
    __shared__ float As[BKT][132];
    __shared__ float Bs[BKT][132];
    __shared__ float2 red[2][BM];

    const int tid  = threadIdx.x;
    const int lane = tid & 31;
    const int warp = tid >> 5;
    const int gid  = lane >> 2;
    const int tig  = lane & 3;
    const int wm   = warp >> 1;   // 0..3 -> m offset wm*32
    const int wn   = warp & 1;    // 0..1 -> n offset wn*64
    const int rowBase = blockIdx.x * BM;

    const float* Aseg[3] = {A0, A1, A2};
    const float* Sseg[3] = {s0, s1, nullptr};

    // per-thread global load coordinates (fixed across iterations)
    const int ar  = tid >> 2;          // A row (i=0); +64 for i=1
    const int ac4 = tid & 3;           // which float4 along BK
    const int bkk = tid >> 5;          // B k row (i=0); +8 for i=1
    const int bn4 = tid & 31;          // which float4 along N

    float acc[2][8][4];
    #pragma unroll
    for (int mt = 0; mt < 2; mt++)
        #pragma unroll
        for (int nt = 0; nt < 8; nt++)
            #pragma unroll
            for (int j = 0; j < 4; j++) acc[mt][nt][j] = 0.0f;

    float4 rA[2]; float rS[2]; float4 rB[2];
    const int K = nseg * 128;
    const int nIter = K >> 4;

#define LOAD_TILE(k0)                                                          \
    {                                                                          \
        int seg = (k0) >> 7, kloc = (k0) & 127;                                \
        const float* A = Aseg[seg];                                            \
        const float* S = Sseg[seg];                                            \
        _Pragma("unroll")                                                      \
        for (int i = 0; i < 2; i++) {                                          \
            int grow = rowBase + ar + i * 64;                                  \
            if (grow < M) {                                                    \
                rA[i] = __ldg((const float4*)(A + (size_t)grow * DD + kloc) + ac4); \
                rS[i] = S ? __ldg(S + grow) : 1.0f;                            \
            } else { rA[i] = make_float4(0.f,0.f,0.f,0.f); rS[i] = 0.0f; }     \
            rB[i] = __ldg((const float4*)(W + (size_t)((k0) + bkk + i * 8) * 128) + bn4); \
        }                                                                      \
    }

#define STORE_TILE()                                                           \
    {                                                                          \
        _Pragma("unroll")                                                      \
        for (int i = 0; i < 2; i++) {                                          \
            int r = ar + i * 64;                                               \
            As[ac4 * 4 + 0][r] = tf32r(rA[i].x * rS[i]);                       \
            As[ac4 * 4 + 1][r] = tf32r(rA[i].y * rS[i]);                       \
            As[ac4 * 4 + 2][r] = tf32r(rA[i].z * rS[i]);                       \
            As[ac4 * 4 + 3][r] = tf32r(rA[i].w * rS[i]);                       \
            float4 t;                                                          \
            t.x = tf32r(rB[i].x); t.y = tf32r(rB[i].y);                        \
            t.z = tf32r(rB[i].z); t.w = tf32r(rB[i].w);                        \
            *(float4*)&Bs[bkk + i * 8][bn4 * 4] = t;                           \
        }                                                                      \
    }

    LOAD_TILE(0);
    STORE_TILE();
    __syncthreads();

    for (int it = 0; it < nIter; it++) {
        if (it + 1 < nIter) LOAD_TILE((it + 1) * BKT);

        #pragma unroll
        for (int ks = 0; ks < BKT; ks += 8) {
            uint32_t a[2][4], b[8][2];
            #pragma unroll
            for (int mt = 0; mt < 2; mt++) {
                int m = wm * 32 + mt * 16 + gid;
                a[mt][0] = fu(As[ks + tig][m]);
                a[mt][1] = fu(As[ks + tig][m + 8]);
                a[mt][2] = fu(As[ks + tig + 4][m]);
                a[mt][3] = fu(As[ks + tig + 4][m + 8]);
            }
            #pragma unroll
            for (int nt = 0; nt < 8; nt++) {
                int n = wn * 64 + nt * 8 + gid;
                b[nt][0] = fu(Bs[ks + tig][n]);
                b[nt][1] = fu(Bs[ks + tig + 4][n]);
            }
            #pragma unroll
            for (int mt = 0; mt < 2; mt++)
                #pragma unroll
                for (int nt = 0; nt < 8; nt++)
                    MMA_TF32(acc[mt][nt], a[mt], b[nt]);
        }
        __syncthreads();
        if (it + 1 < nIter) {
            STORE_TILE();
            __syncthreads();
        }
    }

    // ---- epilogue: bias + LayerNorm + ReLU ----
    // add bias
    #pragma unroll
    for (int nt = 0; nt < 8; nt++) {
        int col = wn * 64 + nt * 8 + tig * 2;
        float2 bv = __ldg((const float2*)(bias + col));
        #pragma unroll
        for (int mt = 0; mt < 2; mt++) {
            acc[mt][nt][0] += bv.x; acc[mt][nt][1] += bv.y;
            acc[mt][nt][2] += bv.x; acc[mt][nt][3] += bv.y;
        }
    }

    // per-thread row partials (rows: wm*32 + mt*16 + gid (+8))
    #pragma unroll
    for (int mt = 0; mt < 2; mt++) {
        float sl = 0.f, ql = 0.f, sh = 0.f, qh = 0.f;
        #pragma unroll
        for (int nt = 0; nt < 8; nt++) {
            sl += acc[mt][nt][0] + acc[mt][nt][1];
            ql += acc[mt][nt][0] * acc[mt][nt][0] + acc[mt][nt][1] * acc[mt][nt][1];
            sh += acc[mt][nt][2] + acc[mt][nt][3];
            qh += acc[mt][nt][2] * acc[mt][nt][2] + acc[mt][nt][3] * acc[mt][nt][3];
        }
        #pragma unroll
        for (int o = 1; o <= 2; o <<= 1) {
            sl += __shfl_xor_sync(0xFFFFFFFFu, sl, o);
            ql += __shfl_xor_sync(0xFFFFFFFFu, ql, o);
            sh += __shfl_xor_sync(0xFFFFFFFFu, sh, o);
            qh += __shfl_xor_sync(0xFFFFFFFFu, qh, o);
        }
        if (tig == 0) {
            int rl = wm * 32 + mt * 16 + gid;
            red[wn][rl]     = make_float2(sl, ql);
            red[wn][rl + 8] = make_float2(sh, qh);
        }
    }
    __syncthreads();

    #pragma unroll
    for (int mt = 0; mt < 2; mt++) {
        int rl = wm * 32 + mt * 16 + gid;
        float2 t0 = red[0][rl], t1 = red[1][rl];
        float ml = (t0.x + t1.x) * (1.0f / 128.0f);
        float vl = (t0.y + t1.y) * (1.0f / 128.0f) - ml * ml;
        float rsl = rsqrtf(vl + 1e-5f);
        float2 u0 = red[0][rl + 8], u1 = red[1][rl + 8];
        float mh = (u0.x + u1.x) * (1.0f / 128.0f);
        float vh = (u0.y + u1.y) * (1.0f / 128.0f) - mh * mh;
        float rsh = rsqrtf(vh + 1e-5f);

        int growl = rowBase + rl;
        int growh = growl + 8;
        #pragma unroll
        for (int nt = 0; nt < 8; nt++) {
            int col = wn * 64 + nt * 8 + tig * 2;
            float2 g2 = __ldg((const float2*)(lng + col));
            float2 b2 = __ldg((const float2*)(lnb + col));
            if (growl < M) {
                float2 o;
                o.x = fmaxf((acc[mt][nt][0] - ml) * rsl * g2.x + b2.x, 0.0f);
                o.y = fmaxf((acc[mt][nt][1] - ml) * rsl * g2.y + b2.y, 0.0f);
                *(float2*)(Cout + (size_t)growl * DD + col) = o;
            }
            if (growh < M) {
                float2 o;
                o.x = fmaxf((acc[mt][nt][2] - mh) * rsh * g2.x + b2.x, 0.0f);
                o.y = fmaxf((acc[mt][nt][3] - mh) * rsh * g2.y + b2.y, 0.0f);
                *(float2*)(Cout + (size_t)growh * DD + col) = o;
            }
        }
    }
#undef LOAD_TILE
#undef STORE_TILE
}

// ---------------- head: out[M,16] = x[M,128] @ Wh[128,16] + bh ----------------
__global__ __launch_bounds__(256) void head_kernel(
    const float* __restrict__ x, const float* __restrict__ Wh,
    const float* __restrict__ bh, float* __restrict__ out, int M)
{
    __shared__ float WsT[16 * 128];
    __shared__ float bs[16];
    for (int i = threadIdx.x; i < 2048; i += 256) {
        int c = i >> 7, k = i & 127;
        WsT[i] = Wh[k * 16 + c];
    }
    if (threadIdx.x < 16) bs[threadIdx.x] = bh[threadIdx.x];
    __syncthreads();
    int warp = threadIdx.x >> 5, lane = threadIdx.x & 31;
    int row = blockIdx.x * 8 + warp;
    if (row >= M) return;
    float4 v = __ldg((const float4*)(x + (size_t)row * DD) + lane);
    float acc[16];
    #pragma unroll
    for (int c = 0; c < 16; c++) {
        float4 w = ((const float4*)(WsT + c * 128))[lane];
        acc[c] = v.x * w.x + v.y * w.y + v.z * w.z + v.w * w.w;
    }
    #pragma unroll
    for (int c = 0; c < 16; c++)
        #pragma unroll
        for (int o = 16; o > 0; o >>= 1)
            acc[c] += __shfl_xor_sync(0xFFFFFFFFu, acc[c], o);
    if (lane == 0) {
        #pragma unroll
        for (int c = 0; c < 16; c++)
            out[(size_t)row * 16 + c] = acc[c] + bs[c];
    }
}

// ---------------- launch ----------------
extern "C" void kernel_launch(void* const* d_in, const int* in_sizes, int n_in,
                              void* d_out, int out_size)
{
    const float* x_paper  = (const float*)d_in[0];
    const float* x_author = (const float*)d_in[1];
    const int*   ei_c     = (const int*)d_in[2];
    const int*   ei_w     = (const int*)d_in[3];
    const int*   ei_r     = (const int*)d_in[4];
    const float* Wl       = (const float*)d_in[5];
    const float* Wr       = (const float*)d_in[6];
    const float* bl       = (const float*)d_in[7];
    const float* lin_p    = (const float*)d_in[8];
    const float* lin_a    = (const float*)d_in[9];
    const float* ln_s     = (const float*)d_in[10];
    const float* ln_b     = (const float*)d_in[11];
    const float* Wh       = (const float*)d_in[12];
    const float* bh       = (const float*)d_in[13];
    float* out = (float*)d_out;

    float *agg1, *agg2, *agga, *cnt1, *cnt2, *cnta, *xp, *xa;
    float *wp_raw, *wp_eff, *wa_raw, *wa_eff, *bp_raw, *bp_eff, *ba_raw, *ba_eff;
    cudaGetSymbolAddress((void**)&agg1, g_agg1);
    cudaGetSymbolAddress((void**)&agg2, g_agg2);
    cudaGetSymbolAddress((void**)&agga, g_agga);
    cudaGetSymbolAddress((void**)&cnt1, g_cnt1);
    cudaGetSymbolAddress((void**)&cnt2, g_cnt2);
    cudaGetSymbolAddress((void**)&cnta, g_cnta);
    cudaGetSymbolAddress((void**)&xp, g_xp);
    cudaGetSymbolAddress((void**)&xa, g_xa);
    cudaGetSymbolAddress((void**)&wp_raw, g_wp_raw);
    cudaGetSymbolAddress((void**)&wp_eff, g_wp_eff);
    cudaGetSymbolAddress((void**)&wa_raw, g_wa_raw);
    cudaGetSymbolAddress((void**)&wa_eff, g_wa_eff);
    cudaGetSymbolAddress((void**)&bp_raw, g_bp_raw);
    cudaGetSymbolAddress((void**)&bp_eff, g_bp_eff);
    cudaGetSymbolAddress((void**)&ba_raw, g_ba_raw);
    cudaGetSymbolAddress((void**)&ba_eff, g_ba_eff);

    const int E = EE;
    // ---- counts (fixed across layers) ----
    cudaMemsetAsync(cnt1, 0, NP * sizeof(float), 0);
    cudaMemsetAsync(cnt2, 0, NP * sizeof(float), 0);
    cudaMemsetAsync(cnta, 0, NA * sizeof(float), 0);
    count_kernel<<<(E + 255) / 256, 256>>>(ei_c + E, cnt1, E);
    count_kernel<<<(E + 255) / 256, 256>>>(ei_w + E, cnt2, E);
    count_kernel<<<(E + 255) / 256, 256>>>(ei_r + E, cnta, E);
    inv_kernel<<<(NP + 255) / 256, 256>>>(cnt1, NP);
    inv_kernel<<<(NP + 255) / 256, 256>>>(cnt2, NP);
    inv_kernel<<<(NA + 255) / 256, 256>>>(cnta, NA);

    int gridP = (NP + BM - 1) / BM;
    int gridA = (NA + BM - 1) / BM;
    int gridScat = (E + 7) / 8;

    // ================= LAYER 0 =================
    prep_w_p<<<(384 * 128) / 256, 256>>>(Wl, Wr, wp_raw, 0);
    prep_w_a<<<(256 * 128) / 256, 256>>>(Wl, Wr, wa_raw, 0);
    prep_bias<<<1, 128>>>(bl, bp_raw, ba_raw, 0);
    fold_w<<<(384 * 128) / 256, 256>>>(wp_raw, lin_p, wp_eff, 384);
    fold_w<<<(256 * 128) / 256, 256>>>(wa_raw, lin_a, wa_eff, 256);
    fold_b<<<1, 128>>>(bp_raw, lin_p, bp_eff);
    fold_b<<<1, 128>>>(ba_raw, lin_a, ba_eff);

    cudaMemsetAsync(agg1, 0, (size_t)NP * DD * sizeof(float), 0);
    cudaMemsetAsync(agg2, 0, (size_t)NP * DD * sizeof(float), 0);
    cudaMemsetAsync(agga, 0, (size_t)NA * DD * sizeof(float), 0);
    scatter_kernel<<<gridScat, 256>>>(x_paper,  ei_c, ei_c + E, agg1, E);
    scatter_kernel<<<gridScat, 256>>>(x_author, ei_w, ei_w + E, agg2, E);
    scatter_kernel<<<gridScat, 256>>>(x_paper,  ei_r, ei_r + E, agga, E);

    gemm_tf32_ln<<<gridP, 256>>>(agg1, agg2, x_paper, cnt1, cnt2, wp_eff, bp_eff,
                                 ln_s + 0, ln_b + 0, xp, NP, 3);
    gemm_tf32_ln<<<gridA, 256>>>(agga, x_author, nullptr, cnta, nullptr, wa_eff, ba_eff,
                                 ln_s + 128, ln_b + 128, xa, NA, 2);

    // ================= LAYER 1 (author path dead -> skipped) =================
    prep_w_p<<<(384 * 128) / 256, 256>>>(Wl, Wr, wp_raw, 1);
    prep_bias<<<1, 128>>>(bl, bp_raw, ba_raw, 1);

    cudaMemsetAsync(agg1, 0, (size_t)NP * DD * sizeof(float), 0);
    cudaMemsetAsync(agg2, 0, (size_t)NP * DD * sizeof(float), 0);
    scatter_kernel<<<gridScat, 256>>>(xp, ei_c, ei_c + E, agg1, E);
    scatter_kernel<<<gridScat, 256>>>(xa, ei_w, ei_w + E, agg2, E);

    gemm_tf32_ln<<<gridP, 256>>>(agg1, agg2, xp, cnt1, cnt2, wp_raw, bp_raw,
                                 ln_s + 256, ln_b + 256, xp, NP, 3);

    // ================= head =================
    head_kernel<<<(NP + 7) / 8, 256>>>(xp, Wh, bh, out, NP);

    (void)in_sizes; (void)n_in; (void)out_size;
}

// round 3
// speedup vs baseline: 1.8959x; 1.2946x over previous
#include <cuda_runtime.h>
#include <cstdint>

#define NP 100000
#define NA 50000
#define DD 128
#define EE 500000

// ---------------- device scratch ----------------
__device__ float g_agg1[(size_t)NP * DD];
__device__ float g_agg2[(size_t)NP * DD];
__device__ float g_agga[(size_t)NA * DD];
__device__ float g_xp[(size_t)NP * DD];
__device__ float g_xa[(size_t)NA * DD];
__device__ float g_wp_raw[384 * 128];
__device__ float g_wp_eff[384 * 128];
__device__ float g_wa_raw[256 * 128];
__device__ float g_wa_eff[256 * 128];
__device__ float g_bp_raw[128];
__device__ float g_bp_eff[128];
__device__ float g_ba_raw[128];
__device__ float g_ba_eff[128];
// CSR structures (built once per call, reused across layers)
__device__ int g_off_c[NP + 1];
__device__ int g_off_w[NP + 1];
__device__ int g_off_r[NA + 1];
__device__ int g_idx_c[EE];
__device__ int g_idx_w[EE];
__device__ int g_idx_r[EE];
__device__ int g_cnt[NP];      // reused scratch for counts
__device__ int g_cur[NP];      // fill cursors
__device__ int g_bsum[128];

// ---------------- helpers ----------------
__device__ __forceinline__ float tf32r(float x) {
    uint32_t u;
    asm("cvt.rna.tf32.f32 %0, %1;" : "=r"(u) : "f"(x));
    return __uint_as_float(u);
}
__device__ __forceinline__ uint32_t fu(float x) { return __float_as_uint(x); }

#define MMA_TF32(c, a, b) \
    asm volatile("mma.sync.aligned.m16n8k8.row.col.f32.tf32.tf32.f32 " \
                 "{%0,%1,%2,%3},{%4,%5,%6,%7},{%8,%9},{%0,%1,%2,%3};" \
                 : "+f"((c)[0]), "+f"((c)[1]), "+f"((c)[2]), "+f"((c)[3]) \
                 : "r"((a)[0]), "r"((a)[1]), "r"((a)[2]), "r"((a)[3]), \
                   "r"((b)[0]), "r"((b)[1]))

// ---------------- CSR build ----------------
__global__ void counti_kernel(const int* __restrict__ dst, int* __restrict__ cnt, int E) {
    int e = blockIdx.x * blockDim.x + threadIdx.x;
    if (e < E) atomicAdd(cnt + dst[e], 1);
}

__global__ void scan_block(const int* __restrict__ cnt, int* __restrict__ off,
                           int* __restrict__ bsum, int n)
{
    __shared__ int sh[1024];
    int tid = threadIdx.x;
    int i = blockIdx.x * 1024 + tid;
    int v = (i < n) ? cnt[i] : 0;
    sh[tid] = v; __syncthreads();
    #pragma unroll
    for (int o = 1; o < 1024; o <<= 1) {
        int t = (tid >= o) ? sh[tid - o] : 0;
        __syncthreads();
        sh[tid] += t;
        __syncthreads();
    }
    if (i < n) off[i] = sh[tid] - v;       // exclusive within block
    if (tid == 1023) bsum[blockIdx.x] = sh[1023];
}

__global__ void scan_bsum(int* __restrict__ bsum, int nb) {
    __shared__ int sh[128];
    int tid = threadIdx.x;
    int v = (tid < nb) ? bsum[tid] : 0;
    sh[tid] = v; __syncthreads();
    #pragma unroll
    for (int o = 1; o < 128; o <<= 1) {
        int t = (tid >= o) ? sh[tid - o] : 0;
        __syncthreads();
        sh[tid] += t;
        __syncthreads();
    }
    if (tid < nb) bsum[tid] = sh[tid] - v; // exclusive
}

__global__ void scan_add(int* __restrict__ off, const int* __restrict__ bsum, int n, int total) {
    int i = blockIdx.x * 1024 + threadIdx.x;
    if (i < n) off[i] += bsum[blockIdx.x];
    if (i == 0) off[n] = total;
}

__global__ void fill_kernel(const int* __restrict__ src, const int* __restrict__ dst,
                            const int* __restrict__ off, int* __restrict__ cur,
                            int* __restrict__ idx, int E)
{
    int e = blockIdx.x * blockDim.x + threadIdx.x;
    if (e >= E) return;
    int d = __ldg(dst + e);
    int p = __ldg(off + d) + atomicAdd(cur + d, 1);
    idx[p] = __ldg(src + e);
}

// ---------------- CSR gather (warp per destination row): mean aggregation ----------------
__global__ __launch_bounds__(256) void gather_kernel(
    const float* __restrict__ x, const int* __restrict__ off,
    const int* __restrict__ idx, float* __restrict__ agg, int N)
{
    int warp = (blockIdx.x * blockDim.x + threadIdx.x) >> 5;
    int lane = threadIdx.x & 31;
    if (warp >= N) return;
    int b = __ldg(off + warp);
    int e = __ldg(off + warp + 1);
    float4 acc = make_float4(0.f, 0.f, 0.f, 0.f);
    int i = b;
    for (; i + 2 <= e; i += 2) {
        int s0 = __ldg(idx + i);
        int s1 = __ldg(idx + i + 1);
        float4 v0 = __ldg((const float4*)(x + (size_t)s0 * DD) + lane);
        float4 v1 = __ldg((const float4*)(x + (size_t)s1 * DD) + lane);
        acc.x += v0.x + v1.x; acc.y += v0.y + v1.y;
        acc.z += v0.z + v1.z; acc.w += v0.w + v1.w;
    }
    if (i < e) {
        int s0 = __ldg(idx + i);
        float4 v0 = __ldg((const float4*)(x + (size_t)s0 * DD) + lane);
        acc.x += v0.x; acc.y += v0.y; acc.z += v0.z; acc.w += v0.w;
    }
    float sc = (e > b) ? __frcp_rn((float)(e - b)) : 0.0f;
    acc.x *= sc; acc.y *= sc; acc.z *= sc; acc.w *= sc;
    ((float4*)(agg + (size_t)warp * DD))[lane] = acc;
}

// ---------------- weight prep ----------------
__global__ void prep_w_p(const float* __restrict__ Wl, const float* __restrict__ Wr,
                         float* __restrict__ wout, int l)
{
    int idx = blockIdx.x * blockDim.x + threadIdx.x;
    if (idx >= 384 * 128) return;
    int k = idx >> 7, j = idx & 127;
    int seg = k >> 7, kk = k & 127;
    float v;
    if (seg == 0)      v = Wl[(size_t)((l * 3 + 0) * 128 + j) * 128 + kk];
    else if (seg == 1) v = Wl[(size_t)((l * 3 + 1) * 128 + j) * 128 + kk];
    else               v = Wr[(size_t)((l * 3 + 0) * 128 + j) * 128 + kk]
                         + Wr[(size_t)((l * 3 + 1) * 128 + j) * 128 + kk];
    wout[idx] = v;
}

__global__ void prep_w_a(const float* __restrict__ Wl, const float* __restrict__ Wr,
                         float* __restrict__ wout, int l)
{
    int idx = blockIdx.x * blockDim.x + threadIdx.x;
    if (idx >= 256 * 128) return;
    int k = idx >> 7, j = idx & 127;
    int seg = k >> 7, kk = k & 127;
    float v;
    if (seg == 0) v = Wl[(size_t)((l * 3 + 2) * 128 + j) * 128 + kk];
    else          v = Wr[(size_t)((l * 3 + 2) * 128 + j) * 128 + kk];
    wout[idx] = v;
}

__global__ void prep_bias(const float* __restrict__ bl, float* __restrict__ bp,
                          float* __restrict__ ba, int l)
{
    int j = threadIdx.x;
    if (j < 128) {
        bp[j] = bl[(l * 3 + 0) * 128 + j] + bl[(l * 3 + 1) * 128 + j];
        ba[j] = bl[(l * 3 + 2) * 128 + j];
    }
}

__global__ void fold_w(const float* __restrict__ win, const float* __restrict__ lin,
                       float* __restrict__ wout, int K)
{
    int idx = blockIdx.x * blockDim.x + threadIdx.x;
    if (idx >= K * 128) return;
    int k = idx >> 7, j = idx & 127;
    const float* wr = win + (size_t)k * 128;
    const float* lr = lin + (size_t)j * 128;
    float s = wr[j];
    #pragma unroll 4
    for (int m = 0; m < 128; m++) s += __ldg(wr + m) * __ldg(lr + m);
    wout[idx] = s;
}

__global__ void fold_b(const float* __restrict__ bin, const float* __restrict__ lin,
                       float* __restrict__ bout)
{
    int j = threadIdx.x;
    if (j >= 128) return;
    const float* lr = lin + (size_t)j * 128;
    float s = bin[j];
    for (int m = 0; m < 128; m++) s += bin[m] * lr[m];
    bout[j] = s;
}

// ---------------- tf32 tensor-core GEMM + fused bias + LayerNorm + ReLU ----------
#define BM 128
#define BKT 16
__global__ __launch_bounds__(256) void gemm_tf32_ln(
    const float* __restrict__ A0, const float* __restrict__ A1, const float* __restrict__ A2,
    const float* __restrict__ W, const float* __restrict__ bias,
    const float* __restrict__ lng, const float* __restrict__ lnb,
    float* __restrict__ Cout, int M, int nseg)
{
    __shared__ float As[BKT][132];
    __shared__ float Bs[BKT][132];
    __shared__ float2 red[2][BM];

    const int tid  = threadIdx.x;
    const int lane = tid & 31;
    const int warp = tid >> 5;
    const int gid  = lane >> 2;
    const int tig  = lane & 3;
    const int wm   = warp >> 1;
    const int wn   = warp & 1;
    const int rowBase = blockIdx.x * BM;

    const float* Aseg[3] = {A0, A1, A2};

    const int ar  = tid >> 2;
    const int ac4 = tid & 3;
    const int bkk = tid >> 5;
    const int bn4 = tid & 31;

    float acc[2][8][4];
    #pragma unroll
    for (int mt = 0; mt < 2; mt++)
        #pragma unroll
        for (int nt = 0; nt < 8; nt++)
            #pragma unroll
            for (int j = 0; j < 4; j++) acc[mt][nt][j] = 0.0f;

    float4 rA[2]; float4 rB[2];
    const int K = nseg * 128;
    const int nIter = K >> 4;

#define LOAD_TILE(k0)                                                          \
    {                                                                          \
        int seg = (k0) >> 7, kloc = (k0) & 127;                                \
        const float* A = Aseg[seg];                                            \
        _Pragma("unroll")                                                      \
        for (int i = 0; i < 2; i++) {                                          \
            int grow = rowBase + ar + i * 64;                                  \
            if (grow < M)                                                      \
                rA[i] = __ldg((const float4*)(A + (size_t)grow * DD + kloc) + ac4); \
            else rA[i] = make_float4(0.f, 0.f, 0.f, 0.f);                      \
            rB[i] = __ldg((const float4*)(W + (size_t)((k0) + bkk + i * 8) * 128) + bn4); \
        }                                                                      \
    }

#define STORE_TILE()                                                           \
    {                                                                          \
        _Pragma("unroll")                                                      \
        for (int i = 0; i < 2; i++) {                                          \
            int r = ar + i * 64;                                               \
            As[ac4 * 4 + 0][r] = tf32r(rA[i].x);                               \
            As[ac4 * 4 + 1][r] = tf32r(rA[i].y);                               \
            As[ac4 * 4 + 2][r] = tf32r(rA[i].z);                               \
            As[ac4 * 4 + 3][r] = tf32r(rA[i].w);                               \
            float4 t;                                                          \
            t.x = tf32r(rB[i].x); t.y = tf32r(rB[i].y);                        \
            t.z = tf32r(rB[i].z); t.w = tf32r(rB[i].w);                        \
            *(float4*)&Bs[bkk + i * 8][bn4 * 4] = t;                           \
        }                                                                      \
    }

    LOAD_TILE(0);
    STORE_TILE();
    __syncthreads();

    for (int it = 0; it < nIter; it++) {
        if (it + 1 < nIter) LOAD_TILE((it + 1) * BKT);

        #pragma unroll
        for (int ks = 0; ks < BKT; ks += 8) {
            uint32_t a[2][4], b[8][2];
            #pragma unroll
            for (int mt = 0; mt < 2; mt++) {
                int m = wm * 32 + mt * 16 + gid;
                a[mt][0] = fu(As[ks + tig][m]);
                a[mt][1] = fu(As[ks + tig][m + 8]);
                a[mt][2] = fu(As[ks + tig + 4][m]);
                a[mt][3] = fu(As[ks + tig + 4][m + 8]);
            }
            #pragma unroll
            for (int nt = 0; nt < 8; nt++) {
                int n = wn * 64 + nt * 8 + gid;
                b[nt][0] = fu(Bs[ks + tig][n]);
                b[nt][1] = fu(Bs[ks + tig + 4][n]);
            }
            #pragma unroll
            for (int mt = 0; mt < 2; mt++)
                #pragma unroll
                for (int nt = 0; nt < 8; nt++)
                    MMA_TF32(acc[mt][nt], a[mt], b[nt]);
        }
        __syncthreads();
        if (it + 1 < nIter) {
            STORE_TILE();
            __syncthreads();
        }
    }

    // ---- epilogue: bias + LayerNorm + ReLU ----
    #pragma unroll
    for (int nt = 0; nt < 8; nt++) {
        int col = wn * 64 + nt * 8 + tig * 2;
        float2 bv = __ldg((const float2*)(bias + col));
        #pragma unroll
        for (int mt = 0; mt < 2; mt++) {
            acc[mt][nt][0] += bv.x; acc[mt][nt][1] += bv.y;
            acc[mt][nt][2] += bv.x; acc[mt][nt][3] += bv.y;
        }
    }

    #pragma unroll
    for (int mt = 0; mt < 2; mt++) {
        float sl = 0.f, ql = 0.f, sh = 0.f, qh = 0.f;
        #pragma unroll
        for (int nt = 0; nt < 8; nt++) {
            sl += acc[mt][nt][0] + acc[mt][nt][1];
            ql += acc[mt][nt][0] * acc[mt][nt][0] + acc[mt][nt][1] * acc[mt][nt][1];
            sh += acc[mt][nt][2] + acc[mt][nt][3];
            qh += acc[mt][nt][2] * acc[mt][nt][2] + acc[mt][nt][3] * acc[mt][nt][3];
        }
        #pragma unroll
        for (int o = 1; o <= 2; o <<= 1) {
            sl += __shfl_xor_sync(0xFFFFFFFFu, sl, o);
            ql += __shfl_xor_sync(0xFFFFFFFFu, ql, o);
            sh += __shfl_xor_sync(0xFFFFFFFFu, sh, o);
            qh += __shfl_xor_sync(0xFFFFFFFFu, qh, o);
        }
        if (tig == 0) {
            int rl = wm * 32 + mt * 16 + gid;
            red[wn][rl]     = make_float2(sl, ql);
            red[wn][rl + 8] = make_float2(sh, qh);
        }
    }
    __syncthreads();

    #pragma unroll
    for (int mt = 0; mt < 2; mt++) {
        int rl = wm * 32 + mt * 16 + gid;
        float2 t0 = red[0][rl], t1 = red[1][rl];
        float ml = (t0.x + t1.x) * (1.0f / 128.0f);
        float vl = (t0.y + t1.y) * (1.0f / 128.0f) - ml * ml;
        float rsl = rsqrtf(vl + 1e-5f);
        float2 u0 = red[0][rl + 8], u1 = red[1][rl + 8];
        float mh = (u0.x + u1.x) * (1.0f / 128.0f);
        float vh = (u0.y + u1.y) * (1.0f / 128.0f) - mh * mh;
        float rsh = rsqrtf(vh + 1e-5f);

        int growl = rowBase + rl;
        int growh = growl + 8;
        #pragma unroll
        for (int nt = 0; nt < 8; nt++) {
            int col = wn * 64 + nt * 8 + tig * 2;
            float2 g2 = __ldg((const float2*)(lng + col));
            float2 b2 = __ldg((const float2*)(lnb + col));
            if (growl < M) {
                float2 o;
                o.x = fmaxf((acc[mt][nt][0] - ml) * rsl * g2.x + b2.x, 0.0f);
                o.y = fmaxf((acc[mt][nt][1] - ml) * rsl * g2.y + b2.y, 0.0f);
                *(float2*)(Cout + (size_t)growl * DD + col) = o;
            }
            if (growh < M) {
                float2 o;
                o.x = fmaxf((acc[mt][nt][2] - mh) * rsh * g2.x + b2.x, 0.0f);
                o.y = fmaxf((acc[mt][nt][3] - mh) * rsh * g2.y + b2.y, 0.0f);
                *(float2*)(Cout + (size_t)growh * DD + col) = o;
            }
        }
    }
#undef LOAD_TILE
#undef STORE_TILE
}

// ---------------- head ----------------
__global__ __launch_bounds__(256) void head_kernel(
    const float* __restrict__ x, const float* __restrict__ Wh,
    const float* __restrict__ bh, float* __restrict__ out, int M)
{
    __shared__ float WsT[16 * 128];
    __shared__ float bs[16];
    for (int i = threadIdx.x; i < 2048; i += 256) {
        int c = i >> 7, k = i & 127;
        WsT[i] = Wh[k * 16 + c];
    }
    if (threadIdx.x < 16) bs[threadIdx.x] = bh[threadIdx.x];
    __syncthreads();
    int warp = threadIdx.x >> 5, lane = threadIdx.x & 31;
    int row = blockIdx.x * 8 + warp;
    if (row >= M) return;
    float4 v = __ldg((const float4*)(x + (size_t)row * DD) + lane);
    float acc[16];
    #pragma unroll
    for (int c = 0; c < 16; c++) {
        float4 w = ((const float4*)(WsT + c * 128))[lane];
        acc[c] = v.x * w.x + v.y * w.y + v.z * w.z + v.w * w.w;
    }
    #pragma unroll
    for (int c = 0; c < 16; c++)
        #pragma unroll
        for (int o = 16; o > 0; o >>= 1)
            acc[c] += __shfl_xor_sync(0xFFFFFFFFu, acc[c], o);
    if (lane == 0) {
        #pragma unroll
        for (int c = 0; c < 16; c++)
            out[(size_t)row * 16 + c] = acc[c] + bs[c];
    }
}

// ---------------- launch ----------------
static void build_csr(const int* ei, int* off, int* idx, int* cnt, int* cur, int* bsum, int n)
{
    const int E = EE;
    cudaMemsetAsync(cnt, 0, n * sizeof(int), 0);
    cudaMemsetAsync(cur, 0, n * sizeof(int), 0);
    counti_kernel<<<(E + 255) / 256, 256>>>(ei + E, cnt, E);
    int nb = (n + 1023) / 1024;
    scan_block<<<nb, 1024>>>(cnt, off, bsum, n);
    scan_bsum<<<1, 128>>>(bsum, nb);
    scan_add<<<nb, 1024>>>(off, bsum, n, E);
    fill_kernel<<<(E + 255) / 256, 256>>>(ei, ei + E, off, cur, idx, E);
}

extern "C" void kernel_launch(void* const* d_in, const int* in_sizes, int n_in,
                              void* d_out, int out_size)
{
    const float* x_paper  = (const float*)d_in[0];
    const float* x_author = (const float*)d_in[1];
    const int*   ei_c     = (const int*)d_in[2];
    const int*   ei_w     = (const int*)d_in[3];
    const int*   ei_r     = (const int*)d_in[4];
    const float* Wl       = (const float*)d_in[5];
    const float* Wr       = (const float*)d_in[6];
    const float* bl       = (const float*)d_in[7];
    const float* lin_p    = (const float*)d_in[8];
    const float* lin_a    = (const float*)d_in[9];
    const float* ln_s     = (const float*)d_in[10];
    const float* ln_b     = (const float*)d_in[11];
    const float* Wh       = (const float*)d_in[12];
    const float* bh       = (const float*)d_in[13];
    float* out = (float*)d_out;

    float *agg1, *agg2, *agga, *xp, *xa;
    float *wp_raw, *wp_eff, *wa_raw, *wa_eff, *bp_raw, *bp_eff, *ba_raw, *ba_eff;
    int *off_c, *off_w, *off_r, *idx_c, *idx_w, *idx_r, *cnt, *cur, *bsum;
    cudaGetSymbolAddress((void**)&agg1, g_agg1);
    cudaGetSymbolAddress((void**)&agg2, g_agg2);
    cudaGetSymbolAddress((void**)&agga, g_agga);
    cudaGetSymbolAddress((void**)&xp, g_xp);
    cudaGetSymbolAddress((void**)&xa, g_xa);
    cudaGetSymbolAddress((void**)&wp_raw, g_wp_raw);
    cudaGetSymbolAddress((void**)&wp_eff, g_wp_eff);
    cudaGetSymbolAddress((void**)&wa_raw, g_wa_raw);
    cudaGetSymbolAddress((void**)&wa_eff, g_wa_eff);
    cudaGetSymbolAddress((void**)&bp_raw, g_bp_raw);
    cudaGetSymbolAddress((void**)&bp_eff, g_bp_eff);
    cudaGetSymbolAddress((void**)&ba_raw, g_ba_raw);
    cudaGetSymbolAddress((void**)&ba_eff, g_ba_eff);
    cudaGetSymbolAddress((void**)&off_c, g_off_c);
    cudaGetSymbolAddress((void**)&off_w, g_off_w);
    cudaGetSymbolAddress((void**)&off_r, g_off_r);
    cudaGetSymbolAddress((void**)&idx_c, g_idx_c);
    cudaGetSymbolAddress((void**)&idx_w, g_idx_w);
    cudaGetSymbolAddress((void**)&idx_r, g_idx_r);
    cudaGetSymbolAddress((void**)&cnt, g_cnt);
    cudaGetSymbolAddress((void**)&cur, g_cur);
    cudaGetSymbolAddress((void**)&bsum, g_bsum);

    // ---- build CSRs (layer-invariant) ----
    build_csr(ei_c, off_c, idx_c, cnt, cur, bsum, NP);
    build_csr(ei_w, off_w, idx_w, cnt, cur, bsum, NP);
    build_csr(ei_r, off_r, idx_r, cnt, cur, bsum, NA);

    int gridP = (NP + BM - 1) / BM;
    int gridA = (NA + BM - 1) / BM;
    int gridGP = (NP * 32 + 255) / 256;
    int gridGA = (NA * 32 + 255) / 256;

    // ---- weight prep (both layers) ----
    prep_w_p<<<(384 * 128) / 256, 256>>>(Wl, Wr, wp_raw, 0);
    prep_w_a<<<(256 * 128) / 256, 256>>>(Wl, Wr, wa_raw, 0);
    prep_bias<<<1, 128>>>(bl, bp_raw, ba_raw, 0);
    fold_w<<<(384 * 128) / 256, 256>>>(wp_raw, lin_p, wp_eff, 384);
    fold_w<<<(256 * 128) / 256, 256>>>(wa_raw, lin_a, wa_eff, 256);
    fold_b<<<1, 128>>>(bp_raw, lin_p, bp_eff);
    fold_b<<<1, 128>>>(ba_raw, lin_a, ba_eff);

    // ================= LAYER 0 =================
    gather_kernel<<<gridGP, 256>>>(x_paper,  off_c, idx_c, agg1, NP);
    gather_kernel<<<gridGP, 256>>>(x_author, off_w, idx_w, agg2, NP);
    gather_kernel<<<gridGA, 256>>>(x_paper,  off_r, idx_r, agga, NA);

    gemm_tf32_ln<<<gridP, 256>>>(agg1, agg2, x_paper, wp_eff, bp_eff,
                                 ln_s + 0, ln_b + 0, xp, NP, 3);
    gemm_tf32_ln<<<gridA, 256>>>(agga, x_author, nullptr, wa_eff, ba_eff,
                                 ln_s + 128, ln_b + 128, xa, NA, 2);

    // ================= LAYER 1 (author path dead -> skipped) =================
    prep_w_p<<<(384 * 128) / 256, 256>>>(Wl, Wr, wp_raw, 1);
    prep_bias<<<1, 128>>>(bl, bp_raw, ba_raw, 1);

    gather_kernel<<<gridGP, 256>>>(xp, off_c, idx_c, agg1, NP);
    gather_kernel<<<gridGP, 256>>>(xa, off_w, idx_w, agg2, NP);

    gemm_tf32_ln<<<gridP, 256>>>(agg1, agg2, xp, wp_raw, bp_raw,
                                 ln_s + 256, ln_b + 256, xp, NP, 3);

    // ================= head =================
    head_kernel<<<(NP + 7) / 8, 256>>>(xp, Wh, bh, out, NP);

    (void)in_sizes; (void)n_in; (void)out_size;
}

// round 4
// speedup vs baseline: 2.0952x; 1.1051x over previous
#include <cuda_runtime.h>
#include <cstdint>

#define NP 100000
#define NA 50000
#define DD 128
#define EE 500000

// ---------------- device scratch ----------------
__device__ float g_agg1[(size_t)NP * DD];
__device__ float g_agg2[(size_t)NP * DD];
__device__ float g_agga[(size_t)NA * DD];
__device__ float g_xp[(size_t)NP * DD];
__device__ float g_xa[(size_t)NA * DD];
__device__ float g_wp_raw[384 * 128];
__device__ float g_wp_eff[384 * 128];
__device__ float g_wa_raw[256 * 128];
__device__ float g_wa_eff[256 * 128];
__device__ float g_bp_raw[128];
__device__ float g_bp_eff[128];
__device__ float g_ba_raw[128];
__device__ float g_ba_eff[128];
// CSR structures (one full set of scratch per edge type -> parallel builds)
__device__ int g_off_c[NP + 1];
__device__ int g_off_w[NP + 1];
__device__ int g_off_r[NA + 1];
__device__ int g_idx_c[EE];
__device__ int g_idx_w[EE];
__device__ int g_idx_r[EE];
__device__ int g_cnt_c[NP];
__device__ int g_cnt_w[NP];
__device__ int g_cnt_r[NA];
__device__ int g_cur_c[NP];
__device__ int g_cur_w[NP];
__device__ int g_cur_r[NA];
__device__ int g_bsum_c[128];
__device__ int g_bsum_w[128];
__device__ int g_bsum_r[128];

// ---------------- streams/events (created once at load; capture-safe fork/join) ----
static cudaStream_t s1, s2, s3;
static cudaEvent_t evRoot, evPrep, evW0, evW1, evA, evP0;
static struct StrInit {
    StrInit() {
        cudaStreamCreateWithFlags(&s1, cudaStreamNonBlocking);
        cudaStreamCreateWithFlags(&s2, cudaStreamNonBlocking);
        cudaStreamCreateWithFlags(&s3, cudaStreamNonBlocking);
        cudaEventCreateWithFlags(&evRoot, cudaEventDisableTiming);
        cudaEventCreateWithFlags(&evPrep, cudaEventDisableTiming);
        cudaEventCreateWithFlags(&evW0,   cudaEventDisableTiming);
        cudaEventCreateWithFlags(&evW1,   cudaEventDisableTiming);
        cudaEventCreateWithFlags(&evA,    cudaEventDisableTiming);
        cudaEventCreateWithFlags(&evP0,   cudaEventDisableTiming);
    }
} s_strInit;

// ---------------- helpers ----------------
__device__ __forceinline__ float tf32r(float x) {
    uint32_t u;
    asm("cvt.rna.tf32.f32 %0, %1;" : "=r"(u) : "f"(x));
    return __uint_as_float(u);
}
__device__ __forceinline__ uint32_t fu(float x) { return __float_as_uint(x); }

#define MMA_TF32(c, a, b) \
    asm volatile("mma.sync.aligned.m16n8k8.row.col.f32.tf32.tf32.f32 " \
                 "{%0,%1,%2,%3},{%4,%5,%6,%7},{%8,%9},{%0,%1,%2,%3};" \
                 : "+f"((c)[0]), "+f"((c)[1]), "+f"((c)[2]), "+f"((c)[3]) \
                 : "r"((a)[0]), "r"((a)[1]), "r"((a)[2]), "r"((a)[3]), \
                   "r"((b)[0]), "r"((b)[1]))

// ---------------- CSR build ----------------
__global__ void counti_kernel(const int* __restrict__ dst, int* __restrict__ cnt, int E) {
    int e = blockIdx.x * blockDim.x + threadIdx.x;
    if (e < E) atomicAdd(cnt + dst[e], 1);
}

__global__ void scan_block(const int* __restrict__ cnt, int* __restrict__ off,
                           int* __restrict__ bsum, int n)
{
    __shared__ int sh[1024];
    int tid = threadIdx.x;
    int i = blockIdx.x * 1024 + tid;
    int v = (i < n) ? cnt[i] : 0;
    sh[tid] = v; __syncthreads();
    #pragma unroll
    for (int o = 1; o < 1024; o <<= 1) {
        int t = (tid >= o) ? sh[tid - o] : 0;
        __syncthreads();
        sh[tid] += t;
        __syncthreads();
    }
    if (i < n) off[i] = sh[tid] - v;
    if (tid == 1023) bsum[blockIdx.x] = sh[1023];
}

__global__ void scan_bsum(int* __restrict__ bsum, int nb) {
    __shared__ int sh[128];
    int tid = threadIdx.x;
    int v = (tid < nb) ? bsum[tid] : 0;
    sh[tid] = v; __syncthreads();
    #pragma unroll
    for (int o = 1; o < 128; o <<= 1) {
        int t = (tid >= o) ? sh[tid - o] : 0;
        __syncthreads();
        sh[tid] += t;
        __syncthreads();
    }
    if (tid < nb) bsum[tid] = sh[tid] - v;
}

__global__ void scan_add(int* __restrict__ off, const int* __restrict__ bsum, int n, int total) {
    int i = blockIdx.x * 1024 + threadIdx.x;
    if (i < n) off[i] += bsum[blockIdx.x];
    if (i == 0) off[n] = total;
}

__global__ void fill_kernel(const int* __restrict__ src, const int* __restrict__ dst,
                            const int* __restrict__ off, int* __restrict__ cur,
                            int* __restrict__ idx, int E)
{
    int e = blockIdx.x * blockDim.x + threadIdx.x;
    if (e >= E) return;
    int d = __ldg(dst + e);
    int p = __ldg(off + d) + atomicAdd(cur + d, 1);
    idx[p] = __ldg(src + e);
}

// ---------------- CSR gather (warp per destination row): mean aggregation ----------------
__global__ __launch_bounds__(256) void gather_kernel(
    const float* __restrict__ x, const int* __restrict__ off,
    const int* __restrict__ idx, float* __restrict__ agg, int N)
{
    int warp = (blockIdx.x * blockDim.x + threadIdx.x) >> 5;
    int lane = threadIdx.x & 31;
    if (warp >= N) return;
    int b = __ldg(off + warp);
    int e = __ldg(off + warp + 1);
    float4 acc = make_float4(0.f, 0.f, 0.f, 0.f);
    int i = b;
    for (; i + 4 <= e; i += 4) {
        int s0 = __ldg(idx + i);
        int s1i = __ldg(idx + i + 1);
        int s2i = __ldg(idx + i + 2);
        int s3i = __ldg(idx + i + 3);
        float4 v0 = __ldg((const float4*)(x + (size_t)s0 * DD) + lane);
        float4 v1 = __ldg((const float4*)(x + (size_t)s1i * DD) + lane);
        float4 v2 = __ldg((const float4*)(x + (size_t)s2i * DD) + lane);
        float4 v3 = __ldg((const float4*)(x + (size_t)s3i * DD) + lane);
        acc.x += (v0.x + v1.x) + (v2.x + v3.x);
        acc.y += (v0.y + v1.y) + (v2.y + v3.y);
        acc.z += (v0.z + v1.z) + (v2.z + v3.z);
        acc.w += (v0.w + v1.w) + (v2.w + v3.w);
    }
    for (; i < e; i++) {
        int s0 = __ldg(idx + i);
        float4 v0 = __ldg((const float4*)(x + (size_t)s0 * DD) + lane);
        acc.x += v0.x; acc.y += v0.y; acc.z += v0.z; acc.w += v0.w;
    }
    float sc = (e > b) ? __frcp_rn((float)(e - b)) : 0.0f;
    acc.x *= sc; acc.y *= sc; acc.z *= sc; acc.w *= sc;
    ((float4*)(agg + (size_t)warp * DD))[lane] = acc;
}

// ---------------- weight prep ----------------
__global__ void prep_w_p(const float* __restrict__ Wl, const float* __restrict__ Wr,
                         float* __restrict__ wout, int l)
{
    int idx = blockIdx.x * blockDim.x + threadIdx.x;
    if (idx >= 384 * 128) return;
    int k = idx >> 7, j = idx & 127;
    int seg = k >> 7, kk = k & 127;
    float v;
    if (seg == 0)      v = Wl[(size_t)((l * 3 + 0) * 128 + j) * 128 + kk];
    else if (seg == 1) v = Wl[(size_t)((l * 3 + 1) * 128 + j) * 128 + kk];
    else               v = Wr[(size_t)((l * 3 + 0) * 128 + j) * 128 + kk]
                         + Wr[(size_t)((l * 3 + 1) * 128 + j) * 128 + kk];
    wout[idx] = v;
}

__global__ void prep_w_a(const float* __restrict__ Wl, const float* __restrict__ Wr,
                         float* __restrict__ wout, int l)
{
    int idx = blockIdx.x * blockDim.x + threadIdx.x;
    if (idx >= 256 * 128) return;
    int k = idx >> 7, j = idx & 127;
    int seg = k >> 7, kk = k & 127;
    float v;
    if (seg == 0) v = Wl[(size_t)((l * 3 + 2) * 128 + j) * 128 + kk];
    else          v = Wr[(size_t)((l * 3 + 2) * 128 + j) * 128 + kk];
    wout[idx] = v;
}

__global__ void prep_bias(const float* __restrict__ bl, float* __restrict__ bp,
                          float* __restrict__ ba, int l)
{
    int j = threadIdx.x;
    if (j < 128) {
        bp[j] = bl[(l * 3 + 0) * 128 + j] + bl[(l * 3 + 1) * 128 + j];
        ba[j] = bl[(l * 3 + 2) * 128 + j];
    }
}

__global__ void fold_w(const float* __restrict__ win, const float* __restrict__ lin,
                       float* __restrict__ wout, int K)
{
    int idx = blockIdx.x * blockDim.x + threadIdx.x;
    if (idx >= K * 128) return;
    int k = idx >> 7, j = idx & 127;
    const float* wr = win + (size_t)k * 128;
    const float* lr = lin + (size_t)j * 128;
    float s = wr[j];
    #pragma unroll 4
    for (int m = 0; m < 128; m++) s += __ldg(wr + m) * __ldg(lr + m);
    wout[idx] = s;
}

__global__ void fold_b(const float* __restrict__ bin, const float* __restrict__ lin,
                       float* __restrict__ bout)
{
    int j = threadIdx.x;
    if (j >= 128) return;
    const float* lr = lin + (size_t)j * 128;
    float s = bin[j];
    for (int m = 0; m < 128; m++) s += bin[m] * lr[m];
    bout[j] = s;
}

// ---------------- tf32 tensor-core GEMM + fused bias + LayerNorm + ReLU ----------
#define BM 128
#define BKT 16
__global__ __launch_bounds__(256) void gemm_tf32_ln(
    const float* __restrict__ A0, const float* __restrict__ A1, const float* __restrict__ A2,
    const float* __restrict__ W, const float* __restrict__ bias,
    const float* __restrict__ lng, const float* __restrict__ lnb,
    float* __restrict__ Cout, int M, int nseg)
{
    __shared__ float As[BKT][132];
    __shared__ float Bs[BKT][132];
    __shared__ float2 red[2][BM];

    const int tid  = threadIdx.x;
    const int lane = tid & 31;
    const int warp = tid >> 5;
    const int gid  = lane >> 2;
    const int tig  = lane & 3;
    const int wm   = warp >> 1;
    const int wn   = warp & 1;
    const int rowBase = blockIdx.x * BM;

    const float* Aseg[3] = {A0, A1, A2};

    const int ar  = tid >> 2;
    const int ac4 = tid & 3;
    const int bkk = tid >> 5;
    const int bn4 = tid & 31;

    float acc[2][8][4];
    #pragma unroll
    for (int mt = 0; mt < 2; mt++)
        #pragma unroll
        for (int nt = 0; nt < 8; nt++)
            #pragma unroll
            for (int j = 0; j < 4; j++) acc[mt][nt][j] = 0.0f;

    float4 rA[2]; float4 rB[2];
    const int K = nseg * 128;
    const int nIter = K >> 4;

#define LOAD_TILE(k0)                                                          \
    {                                                                          \
        int seg = (k0) >> 7, kloc = (k0) & 127;                                \
        const float* A = Aseg[seg];                                            \
        _Pragma("unroll")                                                      \
        for (int i = 0; i < 2; i++) {                                          \
            int grow = rowBase + ar + i * 64;                                  \
            if (grow < M)                                                      \
                rA[i] = __ldg((const float4*)(A + (size_t)grow * DD + kloc) + ac4); \
            else rA[i] = make_float4(0.f, 0.f, 0.f, 0.f);                      \
            rB[i] = __ldg((const float4*)(W + (size_t)((k0) + bkk + i * 8) * 128) + bn4); \
        }                                                                      \
    }

#define STORE_TILE()                                                           \
    {                                                                          \
        _Pragma("unroll")                                                      \
        for (int i = 0; i < 2; i++) {                                          \
            int r = ar + i * 64;                                               \
            As[ac4 * 4 + 0][r] = tf32r(rA[i].x);                               \
            As[ac4 * 4 + 1][r] = tf32r(rA[i].y);                               \
            As[ac4 * 4 + 2][r] = tf32r(rA[i].z);                               \
            As[ac4 * 4 + 3][r] = tf32r(rA[i].w);                               \
            float4 t;                                                          \
            t.x = tf32r(rB[i].x); t.y = tf32r(rB[i].y);                        \
            t.z = tf32r(rB[i].z); t.w = tf32r(rB[i].w);                        \
            *(float4*)&Bs[bkk + i * 8][bn4 * 4] = t;                           \
        }                                                                      \
    }

    LOAD_TILE(0);
    STORE_TILE();
    __syncthreads();

    for (int it = 0; it < nIter; it++) {
        if (it + 1 < nIter) LOAD_TILE((it + 1) * BKT);

        #pragma unroll
        for (int ks = 0; ks < BKT; ks += 8) {
            uint32_t a[2][4], b[8][2];
            #pragma unroll
            for (int mt = 0; mt < 2; mt++) {
                int m = wm * 32 + mt * 16 + gid;
                a[mt][0] = fu(As[ks + tig][m]);
                a[mt][1] = fu(As[ks + tig][m + 8]);
                a[mt][2] = fu(As[ks + tig + 4][m]);
                a[mt][3] = fu(As[ks + tig + 4][m + 8]);
            }
            #pragma unroll
            for (int nt = 0; nt < 8; nt++) {
                int n = wn * 64 + nt * 8 + gid;
                b[nt][0] = fu(Bs[ks + tig][n]);
                b[nt][1] = fu(Bs[ks + tig + 4][n]);
            }
            #pragma unroll
            for (int mt = 0; mt < 2; mt++)
                #pragma unroll
                for (int nt = 0; nt < 8; nt++)
                    MMA_TF32(acc[mt][nt], a[mt], b[nt]);
        }
        __syncthreads();
        if (it + 1 < nIter) {
            STORE_TILE();
            __syncthreads();
        }
    }

    // ---- epilogue: bias + LayerNorm + ReLU ----
    #pragma unroll
    for (int nt = 0; nt < 8; nt++) {
        int col = wn * 64 + nt * 8 + tig * 2;
        float2 bv = __ldg((const float2*)(bias + col));
        #pragma unroll
        for (int mt = 0; mt < 2; mt++) {
            acc[mt][nt][0] += bv.x; acc[mt][nt][1] += bv.y;
            acc[mt][nt][2] += bv.x; acc[mt][nt][3] += bv.y;
        }
    }

    #pragma unroll
    for (int mt = 0; mt < 2; mt++) {
        float sl = 0.f, ql = 0.f, sh = 0.f, qh = 0.f;
        #pragma unroll
        for (int nt = 0; nt < 8; nt++) {
            sl += acc[mt][nt][0] + acc[mt][nt][1];
            ql += acc[mt][nt][0] * acc[mt][nt][0] + acc[mt][nt][1] * acc[mt][nt][1];
            sh += acc[mt][nt][2] + acc[mt][nt][3];
            qh += acc[mt][nt][2] * acc[mt][nt][2] + acc[mt][nt][3] * acc[mt][nt][3];
        }
        #pragma unroll
        for (int o = 1; o <= 2; o <<= 1) {
            sl += __shfl_xor_sync(0xFFFFFFFFu, sl, o);
            ql += __shfl_xor_sync(0xFFFFFFFFu, ql, o);
            sh += __shfl_xor_sync(0xFFFFFFFFu, sh, o);
            qh += __shfl_xor_sync(0xFFFFFFFFu, qh, o);
        }
        if (tig == 0) {
            int rl = wm * 32 + mt * 16 + gid;
            red[wn][rl]     = make_float2(sl, ql);
            red[wn][rl + 8] = make_float2(sh, qh);
        }
    }
    __syncthreads();

    #pragma unroll
    for (int mt = 0; mt < 2; mt++) {
        int rl = wm * 32 + mt * 16 + gid;
        float2 t0 = red[0][rl], t1 = red[1][rl];
        float ml = (t0.x + t1.x) * (1.0f / 128.0f);
        float vl = (t0.y + t1.y) * (1.0f / 128.0f) - ml * ml;
        float rsl = rsqrtf(vl + 1e-5f);
        float2 u0 = red[0][rl + 8], u1 = red[1][rl + 8];
        float mh = (u0.x + u1.x) * (1.0f / 128.0f);
        float vh = (u0.y + u1.y) * (1.0f / 128.0f) - mh * mh;
        float rsh = rsqrtf(vh + 1e-5f);

        int growl = rowBase + rl;
        int growh = growl + 8;
        #pragma unroll
        for (int nt = 0; nt < 8; nt++) {
            int col = wn * 64 + nt * 8 + tig * 2;
            float2 g2 = __ldg((const float2*)(lng + col));
            float2 b2 = __ldg((const float2*)(lnb + col));
            if (growl < M) {
                float2 o;
                o.x = fmaxf((acc[mt][nt][0] - ml) * rsl * g2.x + b2.x, 0.0f);
                o.y = fmaxf((acc[mt][nt][1] - ml) * rsl * g2.y + b2.y, 0.0f);
                *(float2*)(Cout + (size_t)growl * DD + col) = o;
            }
            if (growh < M) {
                float2 o;
                o.x = fmaxf((acc[mt][nt][2] - mh) * rsh * g2.x + b2.x, 0.0f);
                o.y = fmaxf((acc[mt][nt][3] - mh) * rsh * g2.y + b2.y, 0.0f);
                *(float2*)(Cout + (size_t)growh * DD + col) = o;
            }
        }
    }
#undef LOAD_TILE
#undef STORE_TILE
}

// ---------------- head ----------------
__global__ __launch_bounds__(256) void head_kernel(
    const float* __restrict__ x, const float* __restrict__ Wh,
    const float* __restrict__ bh, float* __restrict__ out, int M)
{
    __shared__ float WsT[16 * 128];
    __shared__ float bs[16];
    for (int i = threadIdx.x; i < 2048; i += 256) {
        int c = i >> 7, k = i & 127;
        WsT[i] = Wh[k * 16 + c];
    }
    if (threadIdx.x < 16) bs[threadIdx.x] = bh[threadIdx.x];
    __syncthreads();
    int warp = threadIdx.x >> 5, lane = threadIdx.x & 31;
    int row = blockIdx.x * 8 + warp;
    if (row >= M) return;
    float4 v = __ldg((const float4*)(x + (size_t)row * DD) + lane);
    float acc[16];
    #pragma unroll
    for (int c = 0; c < 16; c++) {
        float4 w = ((const float4*)(WsT + c * 128))[lane];
        acc[c] = v.x * w.x + v.y * w.y + v.z * w.z + v.w * w.w;
    }
    #pragma unroll
    for (int c = 0; c < 16; c++)
        #pragma unroll
        for (int o = 16; o > 0; o >>= 1)
            acc[c] += __shfl_xor_sync(0xFFFFFFFFu, acc[c], o);
    if (lane == 0) {
        #pragma unroll
        for (int c = 0; c < 16; c++)
            out[(size_t)row * 16 + c] = acc[c] + bs[c];
    }
}

// ---------------- launch ----------------
static void build_csr(const int* ei, int* off, int* idx, int* cnt, int* cur, int* bsum,
                      int n, cudaStream_t st)
{
    const int E = EE;
    cudaMemsetAsync(cnt, 0, n * sizeof(int), st);
    cudaMemsetAsync(cur, 0, n * sizeof(int), st);
    counti_kernel<<<(E + 255) / 256, 256, 0, st>>>(ei + E, cnt, E);
    int nb = (n + 1023) / 1024;
    scan_block<<<nb, 1024, 0, st>>>(cnt, off, bsum, n);
    scan_bsum<<<1, 128, 0, st>>>(bsum, nb);
    scan_add<<<nb, 1024, 0, st>>>(off, bsum, n, E);
    fill_kernel<<<(E + 255) / 256, 256, 0, st>>>(ei, ei + E, off, cur, idx, E);
}

extern "C" void kernel_launch(void* const* d_in, const int* in_sizes, int n_in,
                              void* d_out, int out_size)
{
    const float* x_paper  = (const float*)d_in[0];
    const float* x_author = (const float*)d_in[1];
    const int*   ei_c     = (const int*)d_in[2];
    const int*   ei_w     = (const int*)d_in[3];
    const int*   ei_r     = (const int*)d_in[4];
    const float* Wl       = (const float*)d_in[5];
    const float* Wr       = (const float*)d_in[6];
    const float* bl       = (const float*)d_in[7];
    const float* lin_p    = (const float*)d_in[8];
    const float* lin_a    = (const float*)d_in[9];
    const float* ln_s     = (const float*)d_in[10];
    const float* ln_b     = (const float*)d_in[11];
    const float* Wh       = (const float*)d_in[12];
    const float* bh       = (const float*)d_in[13];
    float* out = (float*)d_out;

    float *agg1, *agg2, *agga, *xp, *xa;
    float *wp_raw, *wp_eff, *wa_raw, *wa_eff, *bp_raw, *bp_eff, *ba_raw, *ba_eff;
    int *off_c, *off_w, *off_r, *idx_c, *idx_w, *idx_r;
    int *cnt_c, *cnt_w, *cnt_r, *cur_c, *cur_w, *cur_r, *bs_c, *bs_w, *bs_r;
    cudaGetSymbolAddress((void**)&agg1, g_agg1);
    cudaGetSymbolAddress((void**)&agg2, g_agg2);
    cudaGetSymbolAddress((void**)&agga, g_agga);
    cudaGetSymbolAddress((void**)&xp, g_xp);
    cudaGetSymbolAddress((void**)&xa, g_xa);
    cudaGetSymbolAddress((void**)&wp_raw, g_wp_raw);
    cudaGetSymbolAddress((void**)&wp_eff, g_wp_eff);
    cudaGetSymbolAddress((void**)&wa_raw, g_wa_raw);
    cudaGetSymbolAddress((void**)&wa_eff, g_wa_eff);
    cudaGetSymbolAddress((void**)&bp_raw, g_bp_raw);
    cudaGetSymbolAddress((void**)&bp_eff, g_bp_eff);
    cudaGetSymbolAddress((void**)&ba_raw, g_ba_raw);
    cudaGetSymbolAddress((void**)&ba_eff, g_ba_eff);
    cudaGetSymbolAddress((void**)&off_c, g_off_c);
    cudaGetSymbolAddress((void**)&off_w, g_off_w);
    cudaGetSymbolAddress((void**)&off_r, g_off_r);
    cudaGetSymbolAddress((void**)&idx_c, g_idx_c);
    cudaGetSymbolAddress((void**)&idx_w, g_idx_w);
    cudaGetSymbolAddress((void**)&idx_r, g_idx_r);
    cudaGetSymbolAddress((void**)&cnt_c, g_cnt_c);
    cudaGetSymbolAddress((void**)&cnt_w, g_cnt_w);
    cudaGetSymbolAddress((void**)&cnt_r, g_cnt_r);
    cudaGetSymbolAddress((void**)&cur_c, g_cur_c);
    cudaGetSymbolAddress((void**)&cur_w, g_cur_w);
    cudaGetSymbolAddress((void**)&cur_r, g_cur_r);
    cudaGetSymbolAddress((void**)&bs_c, g_bsum_c);
    cudaGetSymbolAddress((void**)&bs_w, g_bsum_w);
    cudaGetSymbolAddress((void**)&bs_r, g_bsum_r);

    const int gridP  = (NP + BM - 1) / BM;
    const int gridA  = (NA + BM - 1) / BM;
    const int gridGP = (NP * 32 + 255) / 256;
    const int gridGA = (NA * 32 + 255) / 256;

    // ---- fork ----
    cudaEventRecord(evRoot, 0);
    cudaStreamWaitEvent(s1, evRoot, 0);
    cudaStreamWaitEvent(s2, evRoot, 0);
    cudaStreamWaitEvent(s3, evRoot, 0);

    // ---- s3: weight prep (both layers) ----
    prep_w_p<<<(384 * 128) / 256, 256, 0, s3>>>(Wl, Wr, wp_raw, 0);
    prep_w_a<<<(256 * 128) / 256, 256, 0, s3>>>(Wl, Wr, wa_raw, 0);
    prep_bias<<<1, 128, 0, s3>>>(bl, bp_raw, ba_raw, 0);
    fold_w<<<(384 * 128) / 256, 256, 0, s3>>>(wp_raw, lin_p, wp_eff, 384);
    fold_w<<<(256 * 128) / 256, 256, 0, s3>>>(wa_raw, lin_a, wa_eff, 256);
    fold_b<<<1, 128, 0, s3>>>(bp_raw, lin_p, bp_eff);
    fold_b<<<1, 128, 0, s3>>>(ba_raw, lin_a, ba_eff);
    prep_w_p<<<(384 * 128) / 256, 256, 0, s3>>>(Wl, Wr, wp_raw, 1);   // after fold read
    prep_bias<<<1, 128, 0, s3>>>(bl, bp_raw, ba_raw, 1);
    cudaEventRecord(evPrep, s3);

    // ---- s0 (capture stream): cites chain ----
    build_csr(ei_c, off_c, idx_c, cnt_c, cur_c, bs_c, NP, 0);
    gather_kernel<<<gridGP, 256>>>(x_paper, off_c, idx_c, agg1, NP);

    // ---- s1: writes chain ----
    build_csr(ei_w, off_w, idx_w, cnt_w, cur_w, bs_w, NP, s1);
    gather_kernel<<<gridGP, 256, 0, s1>>>(x_author, off_w, idx_w, agg2, NP);
    cudaEventRecord(evW0, s1);

    // ---- s2: author branch ----
    build_csr(ei_r, off_r, idx_r, cnt_r, cur_r, bs_r, NA, s2);
    gather_kernel<<<gridGA, 256, 0, s2>>>(x_paper, off_r, idx_r, agga, NA);
    cudaStreamWaitEvent(s2, evPrep, 0);
    gemm_tf32_ln<<<gridA, 256, 0, s2>>>(agga, x_author, nullptr, wa_eff, ba_eff,
                                        ln_s + 128, ln_b + 128, xa, NA, 2);
    cudaEventRecord(evA, s2);

    // ---- s0: paper GEMM layer 0 ----
    cudaStreamWaitEvent(0, evW0, 0);
    cudaStreamWaitEvent(0, evPrep, 0);
    gemm_tf32_ln<<<gridP, 256>>>(agg1, agg2, x_paper, wp_eff, bp_eff,
                                 ln_s + 0, ln_b + 0, xp, NP, 3);
    cudaEventRecord(evP0, 0);

    // ---- layer-1 gathers: cites(xp) on s0, writes(xa) on s1 ----
    gather_kernel<<<gridGP, 256>>>(xp, off_c, idx_c, agg1, NP);
    cudaStreamWaitEvent(s1, evA, 0);    // xa ready
    cudaStreamWaitEvent(s1, evP0, 0);   // agg2 no longer read by GEMM_P0
    gather_kernel<<<gridGP, 256, 0, s1>>>(xa, off_w, idx_w, agg2, NP);
    cudaEventRecord(evW1, s1);

    // ---- s0: paper GEMM layer 1 + head ----
    cudaStreamWaitEvent(0, evW1, 0);
    gemm_tf32_ln<<<gridP, 256>>>(agg1, agg2, xp, wp_raw, bp_raw,
                                 ln_s + 256, ln_b + 256, xp, NP, 3);
    head_kernel<<<(NP + 7) / 8, 256>>>(xp, Wh, bh, out, NP);

    (void)in_sizes; (void)n_in; (void)out_size;
}